// round 7
// baseline (speedup 1.0000x reference)
#include <cuda_runtime.h>
#include <cuda_fp16.h>
#include <cstdint>

// ---------------- problem constants ----------------
#define BDIM   4096
#define IDIM   256
#define ODIM   256
#define KBASIS (IDIM * 64)           // 16384
#define KTOT   (KBASIS + 2 * IDIM)   // 16896
#define NTOT   (2 * ODIM)            // 512

// GEMM tiling
#define MTILE  128
#define NTILE  128
#define KC     64                    // halves per stage-row = 128 B
#define STAGES 4
#define NST    (KTOT / KC)           // 264 (stages 0..255 basis, 256..263 silu)

// ---------------- scratch (device globals; no allocs allowed) ----------------
__device__ __align__(16) __half g_EU[(size_t)BDIM * IDIM * 8];   // 16 MB [b][i][u]
__device__ __align__(16) __half g_EV[(size_t)BDIM * IDIM * 8];   // 16 MB [b][i][v]
__device__ __align__(16) __half g_Asilu[(size_t)BDIM * 512];     // 4 MB  [b][j]
__device__ __align__(16) __half g_Wt[(size_t)NTOT * KTOT];       // 17.3 MB [n][k] K-major
__device__ float g_bias[NTOT];

// ---------------- helpers ----------------
__device__ __forceinline__ uint32_t smem_u32(const void* p) {
    uint32_t a;
    asm("{ .reg .u64 t; cvta.to.shared.u64 t, %1; cvt.u32.u64 %0, t; }" : "=r"(a) : "l"(p));
    return a;
}

__device__ __forceinline__ void cp16s(uint32_t sm, const void* gm) {
    asm volatile("cp.async.cg.shared.global [%0], [%1], 16;\n" :: "r"(sm), "l"(gm) : "memory");
}

__device__ __forceinline__ void sts128(uint32_t sm, uint32_t a, uint32_t b, uint32_t c, uint32_t d) {
    asm volatile("st.shared.v4.b32 [%0], {%1,%2,%3,%4};" :: "r"(sm), "r"(a), "r"(b), "r"(c), "r"(d) : "memory");
}

__device__ __forceinline__ void ldsm4(uint32_t* r, uint32_t addr) {
    asm volatile("ldmatrix.sync.aligned.m8n8.x4.shared.b16 {%0,%1,%2,%3}, [%4];"
                 : "=r"(r[0]), "=r"(r[1]), "=r"(r[2]), "=r"(r[3]) : "r"(addr));
}

__device__ __forceinline__ void mma_f16(float* d, const uint32_t* a, uint32_t b0, uint32_t b1) {
    asm volatile(
        "mma.sync.aligned.m16n8k16.row.col.f32.f16.f16.f32 "
        "{%0,%1,%2,%3},{%4,%5,%6,%7},{%8,%9},{%0,%1,%2,%3};"
        : "+f"(d[0]), "+f"(d[1]), "+f"(d[2]), "+f"(d[3])
        : "r"(a[0]), "r"(a[1]), "r"(a[2]), "r"(a[3]), "r"(b0), "r"(b1));
}

// ---------------- P1: fused exp tables + silu rows ----------------
// grid 4096 (one b per block), 256 threads (one i per thread). All I/O coalesced.
__global__ void x_kernel(const float* __restrict__ xre, const float* __restrict__ xim) {
    const int b = blockIdx.x;
    const int i = threadIdx.x;
    const float xr = xre[b * IDIM + i];
    const float xi = xim[b * IDIM + i];

    __half eu[8], ev[8];
#pragma unroll
    for (int u = 0; u < 8; u++) {
        float lu = -2.0f + (float)u * (4.0f / 7.0f);
        float dr = xr - lu;
        float di = xi - lu;
        eu[u] = __float2half_rn(__expf(-dr * dr));
        ev[u] = __float2half_rn(__expf(-di * di));
    }
    const size_t off = ((size_t)b * IDIM + i) * 8;
    *(uint4*)&g_EU[off] = *(const uint4*)eu;
    *(uint4*)&g_EV[off] = *(const uint4*)ev;

    g_Asilu[(size_t)b * 512 + i]       = __float2half_rn(xr / (1.0f + __expf(-xr)));
    g_Asilu[(size_t)b * 512 + 256 + i] = __float2half_rn(xi / (1.0f + __expf(-xi)));
}

// ---------------- P2: weights -> Wt[n][k] K-major fp16 ----------------
__global__ void wt_kernel(const float* __restrict__ rw, const float* __restrict__ cw) {
    int idx = blockIdx.x * 256 + threadIdx.x;   // 512*256*16
    int f4 = idx & 15;
    int i  = (idx >> 4) & 255;
    int n  = idx >> 12;               // 0..511
    int o = n >> 1, c = n & 1;
    const float* src = c ? cw : rw;
    float4 w = *(const float4*)&src[((size_t)(i * ODIM + o)) * 64 + f4 * 4];
    size_t dst = (size_t)n * KTOT + i * 64 + f4 * 4;
    *(__half2*)&g_Wt[dst]     = __floats2half2_rn(w.x, w.y);
    *(__half2*)&g_Wt[dst + 2] = __floats2half2_rn(w.z, w.w);
}

// ---------------- P2b: silu weight cols of Wt ----------------
__global__ void wtsilu_kernel(const float* __restrict__ swre, const float* __restrict__ swim) {
    int idx = blockIdx.x * 256 + threadIdx.x;   // 512*512
    int j = idx & 511;
    int n = idx >> 9;
    int o = n >> 1, c = n & 1;
    float v;
    if (j < 256) { int i = j;       v = c ? swim[i * ODIM + o] : swre[i * ODIM + o]; }
    else         { int i = j - 256; v = c ? swre[i * ODIM + o] : -swim[i * ODIM + o]; }
    g_Wt[(size_t)n * KTOT + KBASIS + j] = __float2half_rn(v);
}

// ---------------- P3: bias sums ----------------
__global__ void bias_kernel(const float* __restrict__ bre, const float* __restrict__ bim) {
    int n = blockIdx.x;
    int o = n >> 1;
    const float* src = (n & 1) ? bim : bre;
    int t = threadIdx.x;
    float v = src[t * ODIM + o];
#pragma unroll
    for (int off = 16; off; off >>= 1) v += __shfl_down_sync(0xffffffffu, v, off);
    __shared__ float red[8];
    if ((t & 31) == 0) red[t >> 5] = v;
    __syncthreads();
    if (t == 0) {
        float s = 0.0f;
#pragma unroll
        for (int w = 0; w < 8; w++) s += red[w];
        g_bias[n] = s;
    }
}

// ---------------- GEMM: fp16 mma.m16n8k16, 128x128 tile, KC=64, 4-stage ----------------
// A-stages 0..255 are expanded in-kernel from eu x ev (rank-1 outer product);
// A-stages 256..263 cp.async from g_Asilu. B always cp.async from g_Wt.
#define STAGE_A     (MTILE * 128)           // 16384 B
#define STAGE_BYTES (2 * STAGE_A)           // 32768 B
#define SMEM_BYTES  (STAGES * STAGE_BYTES)  // 131072 B

__device__ __forceinline__ void produce_stage(uint32_t sbase, int m0, int n0, int kt, int buf, int tid) {
    uint32_t sa  = sbase + buf * STAGE_BYTES;
    uint32_t sbb = sa + STAGE_A;

    if (kt < 256) {
        // expand A: row r, chunks c = hf*4..hf*4+3 ; chunk c = eu[c] * ev[0..7]
        const int r  = tid >> 1;
        const int hf = tid & 1;
        const size_t toff = ((size_t)(m0 + r) * IDIM + kt) * 8;
        __half2 ev[4];
        *(uint4*)ev = *(const uint4*)&g_EV[toff];
        __half eu[4];
        *(uint2*)eu = *(const uint2*)&g_EU[toff + hf * 4];
        const uint32_t rowbase = sa + (uint32_t)r * 128;
#pragma unroll
        for (int j = 0; j < 4; j++) {
            const int c = hf * 4 + j;
            const __half2 bb = __half2half2(eu[j]);
            __half2 p0 = __hmul2(bb, ev[0]);
            __half2 p1 = __hmul2(bb, ev[1]);
            __half2 p2 = __hmul2(bb, ev[2]);
            __half2 p3 = __hmul2(bb, ev[3]);
            uint32_t off = rowbase + (uint32_t)((c ^ (r & 7)) * 16);
            sts128(off, *(uint32_t*)&p0, *(uint32_t*)&p1, *(uint32_t*)&p2, *(uint32_t*)&p3);
        }
    } else {
        // silu rows via cp.async
        const __half* Ap = g_Asilu + (size_t)m0 * 512 + (kt - 256) * 64;
#pragma unroll
        for (int j = 0; j < 4; j++) {
            int id = tid + 256 * j;
            int r = id >> 3, c = id & 7;
            uint32_t off = (uint32_t)(r * 128 + ((c ^ (r & 7)) * 16));
            cp16s(sa + off, Ap + (size_t)r * 512 + c * 8);
        }
    }

    const __half* Bp = g_Wt + (size_t)n0 * KTOT + (size_t)kt * KC;
#pragma unroll
    for (int j = 0; j < 4; j++) {
        int id = tid + 256 * j;
        int r = id >> 3, c = id & 7;
        uint32_t off = (uint32_t)(r * 128 + ((c ^ (r & 7)) * 16));
        cp16s(sbb + off, Bp + (size_t)r * KTOT + c * 8);
    }
    asm volatile("cp.async.commit_group;" ::: "memory");
}

__global__ __launch_bounds__(256, 1) void gemm_kernel(float* __restrict__ out) {
    extern __shared__ char smem_raw[];
    const uint32_t sb = smem_u32(smem_raw);

    const int tid  = threadIdx.x;
    const int lane = tid & 31;
    const int warp = tid >> 5;
    const int wm   = warp & 1;        // 2 warp-rows of 64
    const int wn   = warp >> 1;       // 4 warp-cols of 32
    const int lr   = lane & 15;
    const int lh   = lane >> 4;
    const int m0   = blockIdx.x * MTILE;
    const int n0   = blockIdx.y * NTILE;

    float acc[4][4][4];
#pragma unroll
    for (int a = 0; a < 4; a++)
#pragma unroll
        for (int b = 0; b < 4; b++)
#pragma unroll
            for (int c = 0; c < 4; c++) acc[a][b][c] = 0.0f;

    // prologue: stages 0..2
    produce_stage(sb, m0, n0, 0, 0, tid);
    produce_stage(sb, m0, n0, 1, 1, tid);
    produce_stage(sb, m0, n0, 2, 2, tid);

    for (int kt = 0; kt < NST; kt++) {
        if (kt < NST - 2)       asm volatile("cp.async.wait_group 2;" ::: "memory");
        else if (kt == NST - 2) asm volatile("cp.async.wait_group 1;" ::: "memory");
        else                    asm volatile("cp.async.wait_group 0;" ::: "memory");
        __syncthreads();

        // refill stage kt+3 (buffer free: last consumed at iteration kt-1, before the sync above)
        if (kt + 3 < NST) produce_stage(sb, m0, n0, kt + 3, (kt + 3) & (STAGES - 1), tid);

        const int buf = kt & (STAGES - 1);
        const uint32_t sa  = sb + buf * STAGE_BYTES;
        const uint32_t sbb = sa + STAGE_A;

#pragma unroll
        for (int ks = 0; ks < 4; ks++) {
            const uint32_t chunk = (uint32_t)(((ks * 2 + lh) ^ (lr & 7)) * 16);
            uint32_t afr[4][4];
#pragma unroll
            for (int mt = 0; mt < 4; mt++) {
                int row = wm * 64 + mt * 16 + lr;
                ldsm4(afr[mt], sa + (uint32_t)row * 128 + chunk);
            }
            uint32_t bfr[2][4];
#pragma unroll
            for (int nb = 0; nb < 2; nb++) {
                int row = wn * 32 + nb * 16 + lr;
                ldsm4(bfr[nb], sbb + (uint32_t)row * 128 + chunk);
            }
#pragma unroll
            for (int mt = 0; mt < 4; mt++)
#pragma unroll
                for (int nt = 0; nt < 4; nt++) {
                    int nb = nt >> 1, hi = nt & 1;
                    mma_f16(acc[mt][nt], afr[mt], bfr[nb][hi], bfr[nb][2 + hi]);
                }
        }
    }

    // epilogue: add bias, write float2 pairs (re, im adjacent)
    const int gid = lane >> 2;
    const int tg  = lane & 3;
#pragma unroll
    for (int mt = 0; mt < 4; mt++) {
#pragma unroll
        for (int nt = 0; nt < 4; nt++) {
            int row = m0 + wm * 64 + mt * 16 + gid;
            int col = n0 + wn * 32 + nt * 8 + tg * 2;
            float2 bb = *(const float2*)&g_bias[col];
            float2 v0 = make_float2(acc[mt][nt][0] + bb.x, acc[mt][nt][1] + bb.y);
            float2 v1 = make_float2(acc[mt][nt][2] + bb.x, acc[mt][nt][3] + bb.y);
            *(float2*)&out[(size_t)row * NTOT + col]       = v0;
            *(float2*)&out[(size_t)(row + 8) * NTOT + col] = v1;
        }
    }
}

// ---------------- launch ----------------
extern "C" void kernel_launch(void* const* d_in, const int* in_sizes, int n_in,
                              void* d_out, int out_size) {
    const float* xre  = (const float*)d_in[0];
    const float* xim  = (const float*)d_in[1];
    const float* rw   = (const float*)d_in[2];
    const float* cw   = (const float*)d_in[3];
    const float* swre = (const float*)d_in[4];
    const float* swim = (const float*)d_in[5];
    const float* bre  = (const float*)d_in[6];
    const float* bim  = (const float*)d_in[7];
    float* out = (float*)d_out;

    static bool attr_set = false;
    if (!attr_set) {
        cudaFuncSetAttribute(gemm_kernel, cudaFuncAttributeMaxDynamicSharedMemorySize, SMEM_BYTES);
        attr_set = true;
    }

    x_kernel<<<BDIM, 256>>>(xre, xim);
    wt_kernel<<<(NTOT * IDIM * 16) / 256, 256>>>(rw, cw);
    wtsilu_kernel<<<(NTOT * 512) / 256, 256>>>(swre, swim);
    bias_kernel<<<NTOT, 256>>>(bre, bim);
    gemm_kernel<<<dim3(BDIM / MTILE, NTOT / NTILE), 256, SMEM_BYTES>>>(out);
}

// round 8
// speedup vs baseline: 1.1528x; 1.1528x over previous
#include <cuda_runtime.h>
#include <cuda_fp16.h>
#include <cstdint>

// ---------------- problem constants ----------------
#define BDIM   4096
#define IDIM   256
#define ODIM   256
#define KBASIS (IDIM * 64)           // 16384
#define KTOT   (KBASIS + 2 * IDIM)   // 16896
#define NTOT   (2 * ODIM)            // 512

// GEMM tiling
#define MTILE  128
#define NTILE  128
#define KC     128                   // halves per stage-row = 256 B
#define STAGES 3
#define NST    (KTOT / KC)           // 132

// ---------------- scratch (device globals; no allocs allowed) ----------------
__device__ __align__(16) __half g_A[(size_t)BDIM * KTOT];    // 138 MB: [b][k] fp16
__device__ __align__(16) __half g_Wt[(size_t)NTOT * KTOT];   // 17.3 MB: [n][k] fp16 (K-major)
__device__ float g_bias[NTOT];

// ---------------- helpers ----------------
__device__ __forceinline__ uint32_t smem_u32(const void* p) {
    uint32_t a;
    asm("{ .reg .u64 t; cvta.to.shared.u64 t, %1; cvt.u32.u64 %0, t; }" : "=r"(a) : "l"(p));
    return a;
}

__device__ __forceinline__ void cp16s(uint32_t sm, const void* gm) {
    asm volatile("cp.async.cg.shared.global [%0], [%1], 16;\n" :: "r"(sm), "l"(gm) : "memory");
}

__device__ __forceinline__ void ldsm4(uint32_t* r, uint32_t addr) {
    asm volatile("ldmatrix.sync.aligned.m8n8.x4.shared.b16 {%0,%1,%2,%3}, [%4];"
                 : "=r"(r[0]), "=r"(r[1]), "=r"(r[2]), "=r"(r[3]) : "r"(addr));
}

__device__ __forceinline__ void mma_f16(float* d, const uint32_t* a, uint32_t b0, uint32_t b1) {
    asm volatile(
        "mma.sync.aligned.m16n8k16.row.col.f32.f16.f16.f32 "
        "{%0,%1,%2,%3},{%4,%5,%6,%7},{%8,%9},{%0,%1,%2,%3};"
        : "+f"(d[0]), "+f"(d[1]), "+f"(d[2]), "+f"(d[3])
        : "r"(a[0]), "r"(a[1]), "r"(a[2]), "r"(a[3]), "r"(b0), "r"(b1));
}

// ---------------- P1: basis rows of A (separable exps), 16B stores ----------------
// grid (4096, 4), 256 threads; block handles 64 i's of one b-row.
__global__ void basis_kernel(const float* __restrict__ xre, const float* __restrict__ xim) {
    __shared__ float eu[64][8];
    __shared__ __half2 ev[64][4];
    const int b  = blockIdx.x;
    const int i0 = blockIdx.y * 64;
    const int t  = threadIdx.x;

    if (t < 128) {
        const int il = t >> 1, comp = t & 1;
        const float x = (comp ? xim : xre)[b * IDIM + i0 + il];
        if (comp == 0) {
#pragma unroll
            for (int u = 0; u < 8; u++) {
                float lu = -2.0f + (float)u * (4.0f / 7.0f);
                float d  = x - lu;
                eu[il][u] = __expf(-d * d);
            }
        } else {
#pragma unroll
            for (int v = 0; v < 4; v++) {
                float l0 = -2.0f + (float)(2 * v) * (4.0f / 7.0f);
                float l1 = l0 + (4.0f / 7.0f);
                float d0 = x - l0, d1 = x - l1;
                ev[il][v] = __floats2half2_rn(__expf(-d0 * d0), __expf(-d1 * d1));
            }
        }
    }
    __syncthreads();

    const size_t base = (size_t)b * KTOT + (size_t)i0 * 64;
#pragma unroll
    for (int h8 = 0; h8 < 2; h8++) {
        int e0 = t * 16 + h8 * 8;          // 8 consecutive elements: same (il,u), v=0..7
        int il = e0 >> 6;
        int u  = (e0 >> 3) & 7;
        __half2 b2 = __float2half2_rn(eu[il][u]);
        __half2 p0 = __hmul2(b2, ev[il][0]);
        __half2 p1 = __hmul2(b2, ev[il][1]);
        __half2 p2 = __hmul2(b2, ev[il][2]);
        __half2 p3 = __hmul2(b2, ev[il][3]);
        uint4 pack;
        pack.x = *(uint32_t*)&p0; pack.y = *(uint32_t*)&p1;
        pack.z = *(uint32_t*)&p2; pack.w = *(uint32_t*)&p3;
        *(uint4*)&g_A[base + e0] = pack;
    }
}

// ---------------- P1b: silu rows of A ----------------
__global__ void silu_kernel(const float* __restrict__ xre, const float* __restrict__ xim) {
    int idx = blockIdx.x * 256 + threadIdx.x;   // 4096*512
    int b = idx >> 9;
    int j = idx & 511;
    float x = (j < 256) ? xre[b * IDIM + j] : xim[b * IDIM + j - 256];
    float s = x / (1.0f + __expf(-x));
    g_A[(size_t)b * KTOT + KBASIS + j] = __float2half_rn(s);
}

// ---------------- P2: weights -> Wt[n][k] K-major fp16 ----------------
__global__ void wt_kernel(const float* __restrict__ rw, const float* __restrict__ cw) {
    int idx = blockIdx.x * 256 + threadIdx.x;   // 512*256*16
    int f4 = idx & 15;
    int i  = (idx >> 4) & 255;
    int n  = idx >> 12;               // 0..511
    int o = n >> 1, c = n & 1;
    const float* src = c ? cw : rw;
    float4 w = *(const float4*)&src[((size_t)(i * ODIM + o)) * 64 + f4 * 4];
    size_t dst = (size_t)n * KTOT + i * 64 + f4 * 4;
    *(__half2*)&g_Wt[dst]     = __floats2half2_rn(w.x, w.y);
    *(__half2*)&g_Wt[dst + 2] = __floats2half2_rn(w.z, w.w);
}

// ---------------- P2b: silu weight cols of Wt ----------------
__global__ void wtsilu_kernel(const float* __restrict__ swre, const float* __restrict__ swim) {
    int idx = blockIdx.x * 256 + threadIdx.x;   // 512*512
    int j = idx & 511;
    int n = idx >> 9;
    int o = n >> 1, c = n & 1;
    float v;
    if (j < 256) { int i = j;       v = c ? swim[i * ODIM + o] : swre[i * ODIM + o]; }
    else         { int i = j - 256; v = c ? swre[i * ODIM + o] : -swim[i * ODIM + o]; }
    g_Wt[(size_t)n * KTOT + KBASIS + j] = __float2half_rn(v);
}

// ---------------- P3: bias sums ----------------
__global__ void bias_kernel(const float* __restrict__ bre, const float* __restrict__ bim) {
    int n = blockIdx.x;
    int o = n >> 1;
    const float* src = (n & 1) ? bim : bre;
    int t = threadIdx.x;
    float v = src[t * ODIM + o];
#pragma unroll
    for (int off = 16; off; off >>= 1) v += __shfl_down_sync(0xffffffffu, v, off);
    __shared__ float red[8];
    if ((t & 31) == 0) red[t >> 5] = v;
    __syncthreads();
    if (t == 0) {
        float s = 0.0f;
#pragma unroll
        for (int w = 0; w < 8; w++) s += red[w];
        g_bias[n] = s;
    }
}

// ---------------- GEMM: fp16 mma.m16n8k16, 128x128 tile, KC=128, 3-stage ----------------
// Row = 256 B = 16 chunks of 16 B; swizzle per 128B half: (c>>3)*128 + ((c&7)^(r&7))*16.
#define STAGE_A     (MTILE * 256)           // 32768 B
#define STAGE_BYTES (2 * STAGE_A)           // 65536 B
#define SMEM_BYTES  (STAGES * STAGE_BYTES)  // 196608 B

__device__ __forceinline__ uint32_t swz(int r, int c) {
    return (uint32_t)(r * 256 + (c >> 3) * 128 + (((c & 7) ^ (r & 7)) * 16));
}

__device__ __forceinline__ void load_stage(uint32_t sbase, int m0, int n0, int kt, int buf, int tid) {
    uint32_t sa  = sbase + buf * STAGE_BYTES;
    uint32_t sbb = sa + STAGE_A;
    const __half* Ap = g_A  + (size_t)m0 * KTOT + (size_t)kt * KC;
    const __half* Bp = g_Wt + (size_t)n0 * KTOT + (size_t)kt * KC;
#pragma unroll
    for (int j = 0; j < 8; j++) {
        int id = tid + 256 * j;                // 2048 chunks of 16B
        int r = id >> 4, c = id & 15;
        cp16s(sa + swz(r, c), Ap + (size_t)r * KTOT + c * 8);
    }
#pragma unroll
    for (int j = 0; j < 8; j++) {
        int id = tid + 256 * j;
        int r = id >> 4, c = id & 15;
        cp16s(sbb + swz(r, c), Bp + (size_t)r * KTOT + c * 8);
    }
    asm volatile("cp.async.commit_group;" ::: "memory");
}

__global__ __launch_bounds__(256, 1) void gemm_kernel(float* __restrict__ out) {
    extern __shared__ char smem_raw[];
    const uint32_t sb = smem_u32(smem_raw);

    const int tid  = threadIdx.x;
    const int lane = tid & 31;
    const int warp = tid >> 5;
    const int wm   = warp & 1;        // 2 warp-rows of 64
    const int wn   = warp >> 1;       // 4 warp-cols of 32
    const int lr   = lane & 15;
    const int lh   = lane >> 4;
    const int m0   = blockIdx.x * MTILE;
    const int n0   = blockIdx.y * NTILE;

    float acc[4][4][4];
#pragma unroll
    for (int a = 0; a < 4; a++)
#pragma unroll
        for (int b = 0; b < 4; b++)
#pragma unroll
            for (int c = 0; c < 4; c++) acc[a][b][c] = 0.0f;

    // prologue: stages 0,1
    load_stage(sb, m0, n0, 0, 0, tid);
    load_stage(sb, m0, n0, 1, 1, tid);

    uint32_t afr[2][4][4];
    uint32_t bfr[2][2][4];

    for (int kt = 0; kt < NST; kt++) {
        if (kt < NST - 1) asm volatile("cp.async.wait_group 1;" ::: "memory");
        else              asm volatile("cp.async.wait_group 0;" ::: "memory");
        __syncthreads();

        // refill stage kt+2 into buffer (kt+2)%3 (consumed at iteration kt-1)
        if (kt + 2 < NST) load_stage(sb, m0, n0, kt + 2, (kt + 2) % STAGES, tid);

        const int buf = kt % STAGES;
        const uint32_t sa  = sb + buf * STAGE_BYTES;
        const uint32_t sbb = sa + STAGE_A;

        // fragment ks=0
        {
            const int c = lh;                              // ks=0: chunks 0,1
            const uint32_t cc = (uint32_t)((c >> 3) * 128 + (((c & 7) ^ (lr & 7)) * 16));
#pragma unroll
            for (int mt = 0; mt < 4; mt++)
                ldsm4(afr[0][mt], sa + (uint32_t)(wm * 64 + mt * 16 + lr) * 256 + cc);
#pragma unroll
            for (int nb = 0; nb < 2; nb++)
                ldsm4(bfr[0][nb], sbb + (uint32_t)(wn * 32 + nb * 16 + lr) * 256 + cc);
        }

#pragma unroll
        for (int ks = 0; ks < 8; ks++) {
            const int cur = ks & 1;
            if (ks < 7) {
                const int nxt = cur ^ 1;
                const int c = (ks + 1) * 2 + lh;
                const uint32_t cc = (uint32_t)((c >> 3) * 128 + (((c & 7) ^ (lr & 7)) * 16));
#pragma unroll
                for (int mt = 0; mt < 4; mt++)
                    ldsm4(afr[nxt][mt], sa + (uint32_t)(wm * 64 + mt * 16 + lr) * 256 + cc);
#pragma unroll
                for (int nb = 0; nb < 2; nb++)
                    ldsm4(bfr[nxt][nb], sbb + (uint32_t)(wn * 32 + nb * 16 + lr) * 256 + cc);
            }
#pragma unroll
            for (int mt = 0; mt < 4; mt++)
#pragma unroll
                for (int nt = 0; nt < 4; nt++) {
                    int nb = nt >> 1, hi = nt & 1;
                    mma_f16(acc[mt][nt], afr[cur][mt], bfr[cur][nb][hi], bfr[cur][nb][2 + hi]);
                }
        }
    }

    // epilogue: add bias, write float2 pairs (re, im adjacent)
    const int gid = lane >> 2;
    const int tg  = lane & 3;
#pragma unroll
    for (int mt = 0; mt < 4; mt++) {
#pragma unroll
        for (int nt = 0; nt < 4; nt++) {
            int row = m0 + wm * 64 + mt * 16 + gid;
            int col = n0 + wn * 32 + nt * 8 + tg * 2;
            float2 bb = *(const float2*)&g_bias[col];
            float2 v0 = make_float2(acc[mt][nt][0] + bb.x, acc[mt][nt][1] + bb.y);
            float2 v1 = make_float2(acc[mt][nt][2] + bb.x, acc[mt][nt][3] + bb.y);
            *(float2*)&out[(size_t)row * NTOT + col]       = v0;
            *(float2*)&out[(size_t)(row + 8) * NTOT + col] = v1;
        }
    }
}

// ---------------- launch ----------------
extern "C" void kernel_launch(void* const* d_in, const int* in_sizes, int n_in,
                              void* d_out, int out_size) {
    const float* xre  = (const float*)d_in[0];
    const float* xim  = (const float*)d_in[1];
    const float* rw   = (const float*)d_in[2];
    const float* cw   = (const float*)d_in[3];
    const float* swre = (const float*)d_in[4];
    const float* swim = (const float*)d_in[5];
    const float* bre  = (const float*)d_in[6];
    const float* bim  = (const float*)d_in[7];
    float* out = (float*)d_out;

    static bool attr_set = false;
    if (!attr_set) {
        cudaFuncSetAttribute(gemm_kernel, cudaFuncAttributeMaxDynamicSharedMemorySize, SMEM_BYTES);
        attr_set = true;
    }

    basis_kernel<<<dim3(4096, 4), 256>>>(xre, xim);
    silu_kernel<<<(BDIM * 512) / 256, 256>>>(xre, xim);
    wt_kernel<<<(NTOT * IDIM * 16) / 256, 256>>>(rw, cw);
    wtsilu_kernel<<<(NTOT * 512) / 256, 256>>>(swre, swim);
    bias_kernel<<<NTOT, 256>>>(bre, bim);
    gemm_kernel<<<dim3(BDIM / MTILE, NTOT / NTILE), 256, SMEM_BYTES>>>(out);
}

// round 10
// speedup vs baseline: 1.1768x; 1.0209x over previous
#include <cuda_runtime.h>
#include <cuda_fp16.h>
#include <cstdint>

// ---------------- problem constants ----------------
#define BDIM   4096
#define IDIM   256
#define ODIM   256
#define KBASIS (IDIM * 64)           // 16384
#define KTOT   (KBASIS + 2 * IDIM)   // 16896
#define NTOT   (2 * ODIM)            // 512

// GEMM tiling
#define MTILE  128
#define NTILE  128
#define KC     128                   // halves per stage-row = 256 B
#define STAGES 3
#define NST    (KTOT / KC)           // 132

// ---------------- scratch (device globals; no allocs allowed) ----------------
__device__ __align__(16) __half g_A[(size_t)BDIM * KTOT];    // 138 MB: [b][k] fp16
__device__ __align__(16) __half g_Wt[(size_t)NTOT * KTOT];   // 17.3 MB: [n][k] fp16 (K-major)
__device__ float g_bias[NTOT];

// ---------------- helpers ----------------
__device__ __forceinline__ uint32_t smem_u32(const void* p) {
    uint32_t a;
    asm("{ .reg .u64 t; cvta.to.shared.u64 t, %1; cvt.u32.u64 %0, t; }" : "=r"(a) : "l"(p));
    return a;
}

__device__ __forceinline__ void cp16s(uint32_t sm, const void* gm) {
    asm volatile("cp.async.cg.shared.global [%0], [%1], 16;\n" :: "r"(sm), "l"(gm) : "memory");
}

__device__ __forceinline__ void ldsm4(uint32_t* r, uint32_t addr) {
    asm volatile("ldmatrix.sync.aligned.m8n8.x4.shared.b16 {%0,%1,%2,%3}, [%4];"
                 : "=r"(r[0]), "=r"(r[1]), "=r"(r[2]), "=r"(r[3]) : "r"(addr));
}

__device__ __forceinline__ void mma_f16(float* d, const uint32_t* a, uint32_t b0, uint32_t b1) {
    asm volatile(
        "mma.sync.aligned.m16n8k16.row.col.f32.f16.f16.f32 "
        "{%0,%1,%2,%3},{%4,%5,%6,%7},{%8,%9},{%0,%1,%2,%3};"
        : "+f"(d[0]), "+f"(d[1]), "+f"(d[2]), "+f"(d[3])
        : "r"(a[0]), "r"(a[1]), "r"(a[2]), "r"(a[3]), "r"(b0), "r"(b1));
}

// ---------------- P1: basis rows of A (separable exps), 16B stores ----------------
__global__ void basis_kernel(const float* __restrict__ xre, const float* __restrict__ xim) {
    __shared__ float eu[64][8];
    __shared__ __half2 ev[64][4];
    const int b  = blockIdx.x;
    const int i0 = blockIdx.y * 64;
    const int t  = threadIdx.x;

    if (t < 128) {
        const int il = t >> 1, comp = t & 1;
        const float x = (comp ? xim : xre)[b * IDIM + i0 + il];
        if (comp == 0) {
#pragma unroll
            for (int u = 0; u < 8; u++) {
                float lu = -2.0f + (float)u * (4.0f / 7.0f);
                float d  = x - lu;
                eu[il][u] = __expf(-d * d);
            }
        } else {
#pragma unroll
            for (int v = 0; v < 4; v++) {
                float l0 = -2.0f + (float)(2 * v) * (4.0f / 7.0f);
                float l1 = l0 + (4.0f / 7.0f);
                float d0 = x - l0, d1 = x - l1;
                ev[il][v] = __floats2half2_rn(__expf(-d0 * d0), __expf(-d1 * d1));
            }
        }
    }
    __syncthreads();

    const size_t base = (size_t)b * KTOT + (size_t)i0 * 64;
#pragma unroll
    for (int h8 = 0; h8 < 2; h8++) {
        int e0 = t * 16 + h8 * 8;
        int il = e0 >> 6;
        int u  = (e0 >> 3) & 7;
        __half2 b2 = __float2half2_rn(eu[il][u]);
        __half2 p0 = __hmul2(b2, ev[il][0]);
        __half2 p1 = __hmul2(b2, ev[il][1]);
        __half2 p2 = __hmul2(b2, ev[il][2]);
        __half2 p3 = __hmul2(b2, ev[il][3]);
        uint4 pack;
        pack.x = *(uint32_t*)&p0; pack.y = *(uint32_t*)&p1;
        pack.z = *(uint32_t*)&p2; pack.w = *(uint32_t*)&p3;
        *(uint4*)&g_A[base + e0] = pack;
    }
}

// ---------------- P1b: silu rows of A ----------------
__global__ void silu_kernel(const float* __restrict__ xre, const float* __restrict__ xim) {
    int idx = blockIdx.x * 256 + threadIdx.x;   // 4096*512
    int b = idx >> 9;
    int j = idx & 511;
    float x = (j < 256) ? xre[b * IDIM + j] : xim[b * IDIM + j - 256];
    float s = x / (1.0f + __expf(-x));
    g_A[(size_t)b * KTOT + KBASIS + j] = __float2half_rn(s);
}

// ---------------- P2: weights -> Wt[n][k] K-major fp16 ----------------
__global__ void wt_kernel(const float* __restrict__ rw, const float* __restrict__ cw) {
    int idx = blockIdx.x * 256 + threadIdx.x;   // 512*256*16
    int f4 = idx & 15;
    int i  = (idx >> 4) & 255;
    int n  = idx >> 12;               // 0..511
    int o = n >> 1, c = n & 1;
    const float* src = c ? cw : rw;
    float4 w = *(const float4*)&src[((size_t)(i * ODIM + o)) * 64 + f4 * 4];
    size_t dst = (size_t)n * KTOT + i * 64 + f4 * 4;
    *(__half2*)&g_Wt[dst]     = __floats2half2_rn(w.x, w.y);
    *(__half2*)&g_Wt[dst + 2] = __floats2half2_rn(w.z, w.w);
}

// ---------------- P2b: silu weight cols of Wt ----------------
__global__ void wtsilu_kernel(const float* __restrict__ swre, const float* __restrict__ swim) {
    int idx = blockIdx.x * 256 + threadIdx.x;   // 512*512
    int j = idx & 511;
    int n = idx >> 9;
    int o = n >> 1, c = n & 1;
    float v;
    if (j < 256) { int i = j;       v = c ? swim[i * ODIM + o] : swre[i * ODIM + o]; }
    else         { int i = j - 256; v = c ? swre[i * ODIM + o] : -swim[i * ODIM + o]; }
    g_Wt[(size_t)n * KTOT + KBASIS + j] = __float2half_rn(v);
}

// ---------------- P3: bias sums ----------------
__global__ void bias_kernel(const float* __restrict__ bre, const float* __restrict__ bim) {
    int n = blockIdx.x;
    int o = n >> 1;
    const float* src = (n & 1) ? bim : bre;
    int t = threadIdx.x;
    float v = src[t * ODIM + o];
#pragma unroll
    for (int off = 16; off; off >>= 1) v += __shfl_down_sync(0xffffffffu, v, off);
    __shared__ float red[8];
    if ((t & 31) == 0) red[t >> 5] = v;
    __syncthreads();
    if (t == 0) {
        float s = 0.0f;
#pragma unroll
        for (int w = 0; w < 8; w++) s += red[w];
        g_bias[n] = s;
    }
}

// ---------------- GEMM: fp16 mma, 128x128 tile, warps = 2x2 spatial x 2 k-slices ----------------
// Each warp: 64x64 spatial tile, half of each KC=128 chunk. Epilogue merges k-slices via smem.
#define STAGE_A     (MTILE * 256)           // 32768 B
#define STAGE_BYTES (2 * STAGE_A)           // 65536 B
#define SMEM_BYTES  (STAGES * STAGE_BYTES)  // 196608 B

__device__ __forceinline__ uint32_t swz(int r, int c) {
    return (uint32_t)(r * 256 + (c >> 3) * 128 + (((c & 7) ^ (r & 7)) * 16));
}

__device__ __forceinline__ void load_stage(uint32_t sbase, int m0, int n0, int kt, int buf, int tid) {
    uint32_t sa  = sbase + buf * STAGE_BYTES;
    uint32_t sbb = sa + STAGE_A;
    const __half* Ap = g_A  + (size_t)m0 * KTOT + (size_t)kt * KC;
    const __half* Bp = g_Wt + (size_t)n0 * KTOT + (size_t)kt * KC;
#pragma unroll
    for (int j = 0; j < 8; j++) {
        int id = tid + 256 * j;                // 2048 chunks of 16B
        int r = id >> 4, c = id & 15;
        cp16s(sa + swz(r, c), Ap + (size_t)r * KTOT + c * 8);
    }
#pragma unroll
    for (int j = 0; j < 8; j++) {
        int id = tid + 256 * j;
        int r = id >> 4, c = id & 15;
        cp16s(sbb + swz(r, c), Bp + (size_t)r * KTOT + c * 8);
    }
    asm volatile("cp.async.commit_group;" ::: "memory");
}

__global__ __launch_bounds__(256, 1) void gemm_kernel(float* __restrict__ out) {
    extern __shared__ char smem_raw[];
    const uint32_t sb = smem_u32(smem_raw);

    const int tid  = threadIdx.x;
    const int lane = tid & 31;
    const int warp = tid >> 5;
    const int kg   = warp >> 2;        // k-slice: 0 -> chunks 0..7, 1 -> chunks 8..15
    const int wm   = (warp >> 1) & 1;  // 2 spatial rows of 64
    const int wn   = warp & 1;         // 2 spatial cols of 64
    const int lr   = lane & 15;
    const int lh   = lane >> 4;
    const int m0   = blockIdx.x * MTILE;
    const int n0   = blockIdx.y * NTILE;

    float acc[4][8][4];
#pragma unroll
    for (int a = 0; a < 4; a++)
#pragma unroll
        for (int b = 0; b < 8; b++)
#pragma unroll
            for (int c = 0; c < 4; c++) acc[a][b][c] = 0.0f;

    // prologue: stages 0,1
    load_stage(sb, m0, n0, 0, 0, tid);
    load_stage(sb, m0, n0, 1, 1, tid);

    uint32_t afr[2][4][4];
    uint32_t bfr[2][4][4];

    for (int kt = 0; kt < NST; kt++) {
        if (kt < NST - 1) asm volatile("cp.async.wait_group 1;" ::: "memory");
        else              asm volatile("cp.async.wait_group 0;" ::: "memory");
        __syncthreads();

        if (kt + 2 < NST) load_stage(sb, m0, n0, kt + 2, (kt + 2) % STAGES, tid);

        const int buf = kt % STAGES;
        const uint32_t sa  = sb + buf * STAGE_BYTES;
        const uint32_t sbb = sa + STAGE_A;

        // fragment ks_local = 0
        {
            const int c = kg * 8 + lh;
            const uint32_t cc = (uint32_t)((c >> 3) * 128 + (((c & 7) ^ (lr & 7)) * 16));
#pragma unroll
            for (int mt = 0; mt < 4; mt++)
                ldsm4(afr[0][mt], sa + (uint32_t)(wm * 64 + mt * 16 + lr) * 256 + cc);
#pragma unroll
            for (int nb = 0; nb < 4; nb++)
                ldsm4(bfr[0][nb], sbb + (uint32_t)(wn * 64 + nb * 16 + lr) * 256 + cc);
        }

#pragma unroll
        for (int ks = 0; ks < 4; ks++) {
            const int cur = ks & 1;
            if (ks < 3) {
                const int nxt = cur ^ 1;
                const int c = kg * 8 + (ks + 1) * 2 + lh;
                const uint32_t cc = (uint32_t)((c >> 3) * 128 + (((c & 7) ^ (lr & 7)) * 16));
#pragma unroll
                for (int mt = 0; mt < 4; mt++)
                    ldsm4(afr[nxt][mt], sa + (uint32_t)(wm * 64 + mt * 16 + lr) * 256 + cc);
#pragma unroll
                for (int nb = 0; nb < 4; nb++)
                    ldsm4(bfr[nxt][nb], sbb + (uint32_t)(wn * 64 + nb * 16 + lr) * 256 + cc);
            }
#pragma unroll
            for (int mt = 0; mt < 4; mt++)
#pragma unroll
                for (int nt = 0; nt < 8; nt++) {
                    int nb = nt >> 1, hi = nt & 1;
                    mma_f16(acc[mt][nt], afr[cur][mt], bfr[cur][nb][hi], bfr[cur][nb][2 + hi]);
                }
        }
    }

    // ---------------- epilogue: merge k-slices via smem ----------------
    __syncthreads();   // all warps done reading stage buffers

    // kg=1 warps dump partials: region per spatial position = 16 KB
    if (kg == 1) {
        float* dst = (float*)(smem_raw + (wm * 2 + wn) * 16384);
#pragma unroll
        for (int mt = 0; mt < 4; mt++)
#pragma unroll
            for (int nt = 0; nt < 8; nt++) {
                float4 v = make_float4(acc[mt][nt][0], acc[mt][nt][1], acc[mt][nt][2], acc[mt][nt][3]);
                *(float4*)&dst[((mt * 8 + nt) * 32 + lane) * 4] = v;
            }
    }
    __syncthreads();

    if (kg == 0) {
        const float* prt = (const float*)(smem_raw + (wm * 2 + wn) * 16384);
        const int gid = lane >> 2;
        const int tg  = lane & 3;
#pragma unroll
        for (int mt = 0; mt < 4; mt++) {
#pragma unroll
            for (int nt = 0; nt < 8; nt++) {
                float4 p = *(const float4*)&prt[((mt * 8 + nt) * 32 + lane) * 4];
                int row = m0 + wm * 64 + mt * 16 + gid;
                int col = n0 + wn * 64 + nt * 8 + tg * 2;
                float2 bb = *(const float2*)&g_bias[col];
                float2 v0 = make_float2(acc[mt][nt][0] + p.x + bb.x, acc[mt][nt][1] + p.y + bb.y);
                float2 v1 = make_float2(acc[mt][nt][2] + p.z + bb.x, acc[mt][nt][3] + p.w + bb.y);
                *(float2*)&out[(size_t)row * NTOT + col]       = v0;
                *(float2*)&out[(size_t)(row + 8) * NTOT + col] = v1;
            }
        }
    }
}

// ---------------- launch ----------------
extern "C" void kernel_launch(void* const* d_in, const int* in_sizes, int n_in,
                              void* d_out, int out_size) {
    const float* xre  = (const float*)d_in[0];
    const float* xim  = (const float*)d_in[1];
    const float* rw   = (const float*)d_in[2];
    const float* cw   = (const float*)d_in[3];
    const float* swre = (const float*)d_in[4];
    const float* swim = (const float*)d_in[5];
    const float* bre  = (const float*)d_in[6];
    const float* bim  = (const float*)d_in[7];
    float* out = (float*)d_out;

    static bool attr_set = false;
    if (!attr_set) {
        cudaFuncSetAttribute(gemm_kernel, cudaFuncAttributeMaxDynamicSharedMemorySize, SMEM_BYTES);
        attr_set = true;
    }

    basis_kernel<<<dim3(4096, 4), 256>>>(xre, xim);
    silu_kernel<<<(BDIM * 512) / 256, 256>>>(xre, xim);
    wt_kernel<<<(NTOT * IDIM * 16) / 256, 256>>>(rw, cw);
    wtsilu_kernel<<<(NTOT * 512) / 256, 256>>>(swre, swim);
    bias_kernel<<<NTOT, 256>>>(bre, bim);
    gemm_kernel<<<dim3(BDIM / MTILE, NTOT / NTILE), 256, SMEM_BYTES>>>(out);
}

// round 11
// speedup vs baseline: 1.2317x; 1.0466x over previous
#include <cuda_runtime.h>
#include <cuda_fp16.h>
#include <cstdint>

// ---------------- problem constants ----------------
#define BDIM   4096
#define IDIM   256
#define ODIM   256
#define KBASIS (IDIM * 64)           // 16384
#define KTOT   (KBASIS + 2 * IDIM)   // 16896
#define NTOT   (2 * ODIM)            // 512

// GEMM tiling
#define MTILE  128
#define NTILE  128
#define KC     128                   // halves per stage-row = 256 B
#define STAGES 3
#define NST    (KTOT / KC)           // 132

// ---------------- scratch (device globals; no allocs allowed) ----------------
__device__ __align__(16) __half g_A[(size_t)BDIM * KTOT];    // 138 MB: [b][k] fp16
__device__ __align__(16) __half g_Wt[(size_t)NTOT * KTOT];   // 17.3 MB: [n][k] fp16 (K-major)
__device__ float g_bias[NTOT];

// ---------------- helpers ----------------
__device__ __forceinline__ uint32_t smem_u32(const void* p) {
    uint32_t a;
    asm("{ .reg .u64 t; cvta.to.shared.u64 t, %1; cvt.u32.u64 %0, t; }" : "=r"(a) : "l"(p));
    return a;
}

__device__ __forceinline__ void cp16s(uint32_t sm, const void* gm) {
    asm volatile("cp.async.cg.shared.global [%0], [%1], 16;\n" :: "r"(sm), "l"(gm) : "memory");
}

__device__ __forceinline__ void ldsm4(uint32_t* r, uint32_t addr) {
    asm volatile("ldmatrix.sync.aligned.m8n8.x4.shared.b16 {%0,%1,%2,%3}, [%4];"
                 : "=r"(r[0]), "=r"(r[1]), "=r"(r[2]), "=r"(r[3]) : "r"(addr));
}

__device__ __forceinline__ void mma_f16(float* d, const uint32_t* a, uint32_t b0, uint32_t b1) {
    asm volatile(
        "mma.sync.aligned.m16n8k16.row.col.f32.f16.f16.f32 "
        "{%0,%1,%2,%3},{%4,%5,%6,%7},{%8,%9},{%0,%1,%2,%3};"
        : "+f"(d[0]), "+f"(d[1]), "+f"(d[2]), "+f"(d[3])
        : "r"(a[0]), "r"(a[1]), "r"(a[2]), "r"(a[3]), "r"(b0), "r"(b1));
}

// ---------------- P1: fused basis + silu rows of A ----------------
// grid (4096, 4), 256 threads; block handles 64 i's of one b-row.
// Blocks with y==0 additionally write the 512 silu entries of their b.
__global__ void prep_x(const float* __restrict__ xre, const float* __restrict__ xim) {
    __shared__ float eu[64][8];
    __shared__ __half2 ev[64][4];
    const int b  = blockIdx.x;
    const int i0 = blockIdx.y * 64;
    const int t  = threadIdx.x;

    if (t < 128) {
        const int il = t >> 1, comp = t & 1;
        const float x = (comp ? xim : xre)[b * IDIM + i0 + il];
        if (comp == 0) {
#pragma unroll
            for (int u = 0; u < 8; u++) {
                float lu = -2.0f + (float)u * (4.0f / 7.0f);
                float d  = x - lu;
                eu[il][u] = __expf(-d * d);
            }
        } else {
#pragma unroll
            for (int v = 0; v < 4; v++) {
                float l0 = -2.0f + (float)(2 * v) * (4.0f / 7.0f);
                float l1 = l0 + (4.0f / 7.0f);
                float d0 = x - l0, d1 = x - l1;
                ev[il][v] = __floats2half2_rn(__expf(-d0 * d0), __expf(-d1 * d1));
            }
        }
    }

    if (blockIdx.y == 0) {
        float xr = xre[b * IDIM + t];
        float xi = xim[b * IDIM + t];
        g_A[(size_t)b * KTOT + KBASIS + t]       = __float2half_rn(xr / (1.0f + __expf(-xr)));
        g_A[(size_t)b * KTOT + KBASIS + 256 + t] = __float2half_rn(xi / (1.0f + __expf(-xi)));
    }
    __syncthreads();

    const size_t base = (size_t)b * KTOT + (size_t)i0 * 64;
#pragma unroll
    for (int h8 = 0; h8 < 2; h8++) {
        int e0 = t * 16 + h8 * 8;
        int il = e0 >> 6;
        int u  = (e0 >> 3) & 7;
        __half2 b2 = __float2half2_rn(eu[il][u]);
        __half2 p0 = __hmul2(b2, ev[il][0]);
        __half2 p1 = __hmul2(b2, ev[il][1]);
        __half2 p2 = __hmul2(b2, ev[il][2]);
        __half2 p3 = __hmul2(b2, ev[il][3]);
        uint4 pack;
        pack.x = *(uint32_t*)&p0; pack.y = *(uint32_t*)&p1;
        pack.z = *(uint32_t*)&p2; pack.w = *(uint32_t*)&p3;
        *(uint4*)&g_A[base + e0] = pack;
    }
}

// ---------------- P2: fused weights + silu-weights + bias ----------------
// grid.x = 8192 (wt) + 1024 (wtsilu) + 512 (bias) = 9728 blocks of 256 threads.
__global__ void prep_w(const float* __restrict__ rw, const float* __restrict__ cw,
                       const float* __restrict__ swre, const float* __restrict__ swim,
                       const float* __restrict__ bre, const float* __restrict__ bim) {
    const int bid = blockIdx.x;
    const int t   = threadIdx.x;

    if (bid < 8192) {
        // weights -> Wt[n][k] K-major fp16
        int idx = bid * 256 + t;          // 512*256*16
        int f4 = idx & 15;
        int i  = (idx >> 4) & 255;
        int n  = idx >> 12;               // 0..511
        int o = n >> 1, c = n & 1;
        const float* src = c ? cw : rw;
        float4 w = *(const float4*)&src[((size_t)(i * ODIM + o)) * 64 + f4 * 4];
        size_t dst = (size_t)n * KTOT + i * 64 + f4 * 4;
        *(__half2*)&g_Wt[dst]     = __floats2half2_rn(w.x, w.y);
        *(__half2*)&g_Wt[dst + 2] = __floats2half2_rn(w.z, w.w);
    } else if (bid < 8192 + 1024) {
        // silu weight cols of Wt
        int idx = (bid - 8192) * 256 + t; // 512*512
        int j = idx & 511;
        int n = idx >> 9;
        int o = n >> 1, c = n & 1;
        float v;
        if (j < 256) { int i = j;       v = c ? swim[i * ODIM + o] : swre[i * ODIM + o]; }
        else         { int i = j - 256; v = c ? swre[i * ODIM + o] : -swim[i * ODIM + o]; }
        g_Wt[(size_t)n * KTOT + KBASIS + j] = __float2half_rn(v);
    } else {
        // bias column sums
        int n = bid - (8192 + 1024);
        int o = n >> 1;
        const float* src = (n & 1) ? bim : bre;
        float v = src[t * ODIM + o];
#pragma unroll
        for (int off = 16; off; off >>= 1) v += __shfl_down_sync(0xffffffffu, v, off);
        __shared__ float red[8];
        if ((t & 31) == 0) red[t >> 5] = v;
        __syncthreads();
        if (t == 0) {
            float s = 0.0f;
#pragma unroll
            for (int w = 0; w < 8; w++) s += red[w];
            g_bias[n] = s;
        }
    }
}

// ---------------- GEMM: fp16 mma, 128x128 tile, warps = 2x2 spatial x 2 k-slices ----------------
#define STAGE_A     (MTILE * 256)           // 32768 B
#define STAGE_BYTES (2 * STAGE_A)           // 65536 B
#define SMEM_BYTES  (STAGES * STAGE_BYTES)  // 196608 B

__device__ __forceinline__ uint32_t swz(int r, int c) {
    return (uint32_t)(r * 256 + (c >> 3) * 128 + (((c & 7) ^ (r & 7)) * 16));
}

__device__ __forceinline__ void load_stage(uint32_t sbase, int m0, int n0, int kt, int buf, int tid) {
    uint32_t sa  = sbase + buf * STAGE_BYTES;
    uint32_t sbb = sa + STAGE_A;
    const __half* Ap = g_A  + (size_t)m0 * KTOT + (size_t)kt * KC;
    const __half* Bp = g_Wt + (size_t)n0 * KTOT + (size_t)kt * KC;
#pragma unroll
    for (int j = 0; j < 8; j++) {
        int id = tid + 256 * j;                // 2048 chunks of 16B
        int r = id >> 4, c = id & 15;
        cp16s(sa + swz(r, c), Ap + (size_t)r * KTOT + c * 8);
    }
#pragma unroll
    for (int j = 0; j < 8; j++) {
        int id = tid + 256 * j;
        int r = id >> 4, c = id & 15;
        cp16s(sbb + swz(r, c), Bp + (size_t)r * KTOT + c * 8);
    }
    asm volatile("cp.async.commit_group;" ::: "memory");
}

__global__ __launch_bounds__(256, 1) void gemm_kernel(float* __restrict__ out) {
    extern __shared__ char smem_raw[];
    const uint32_t sb = smem_u32(smem_raw);

    const int tid  = threadIdx.x;
    const int lane = tid & 31;
    const int warp = tid >> 5;
    const int kg   = warp >> 2;        // k-slice: 0 -> chunks 0..7, 1 -> chunks 8..15
    const int wm   = (warp >> 1) & 1;  // 2 spatial rows of 64
    const int wn   = warp & 1;         // 2 spatial cols of 64
    const int lr   = lane & 15;
    const int lh   = lane >> 4;
    // n fastest in blockIdx.x so the 4 CTAs sharing an A-slice are adjacent
    const int n0   = blockIdx.x * NTILE;
    const int m0   = blockIdx.y * MTILE;

    float acc[4][8][4];
#pragma unroll
    for (int a = 0; a < 4; a++)
#pragma unroll
        for (int b = 0; b < 8; b++)
#pragma unroll
            for (int c = 0; c < 4; c++) acc[a][b][c] = 0.0f;

    // prologue: stages 0,1
    load_stage(sb, m0, n0, 0, 0, tid);
    load_stage(sb, m0, n0, 1, 1, tid);

    uint32_t afr[2][4][4];
    uint32_t bfr[2][4][4];

    for (int kt = 0; kt < NST; kt++) {
        if (kt < NST - 1) asm volatile("cp.async.wait_group 1;" ::: "memory");
        else              asm volatile("cp.async.wait_group 0;" ::: "memory");
        __syncthreads();

        if (kt + 2 < NST) load_stage(sb, m0, n0, kt + 2, (kt + 2) % STAGES, tid);

        const int buf = kt % STAGES;
        const uint32_t sa  = sb + buf * STAGE_BYTES;
        const uint32_t sbb = sa + STAGE_A;

        // fragment ks_local = 0
        {
            const int c = kg * 8 + lh;
            const uint32_t cc = (uint32_t)((c >> 3) * 128 + (((c & 7) ^ (lr & 7)) * 16));
#pragma unroll
            for (int mt = 0; mt < 4; mt++)
                ldsm4(afr[0][mt], sa + (uint32_t)(wm * 64 + mt * 16 + lr) * 256 + cc);
#pragma unroll
            for (int nb = 0; nb < 4; nb++)
                ldsm4(bfr[0][nb], sbb + (uint32_t)(wn * 64 + nb * 16 + lr) * 256 + cc);
        }

#pragma unroll
        for (int ks = 0; ks < 4; ks++) {
            const int cur = ks & 1;
            if (ks < 3) {
                const int nxt = cur ^ 1;
                const int c = kg * 8 + (ks + 1) * 2 + lh;
                const uint32_t cc = (uint32_t)((c >> 3) * 128 + (((c & 7) ^ (lr & 7)) * 16));
#pragma unroll
                for (int mt = 0; mt < 4; mt++)
                    ldsm4(afr[nxt][mt], sa + (uint32_t)(wm * 64 + mt * 16 + lr) * 256 + cc);
#pragma unroll
                for (int nb = 0; nb < 4; nb++)
                    ldsm4(bfr[nxt][nb], sbb + (uint32_t)(wn * 64 + nb * 16 + lr) * 256 + cc);
            }
#pragma unroll
            for (int mt = 0; mt < 4; mt++)
#pragma unroll
                for (int nt = 0; nt < 8; nt++) {
                    int nb = nt >> 1, hi = nt & 1;
                    mma_f16(acc[mt][nt], afr[cur][mt], bfr[cur][nb][hi], bfr[cur][nb][2 + hi]);
                }
        }
    }

    // ---------------- epilogue: merge k-slices via smem ----------------
    __syncthreads();   // all warps done reading stage buffers

    if (kg == 1) {
        float* dst = (float*)(smem_raw + (wm * 2 + wn) * 16384);
#pragma unroll
        for (int mt = 0; mt < 4; mt++)
#pragma unroll
            for (int nt = 0; nt < 8; nt++) {
                float4 v = make_float4(acc[mt][nt][0], acc[mt][nt][1], acc[mt][nt][2], acc[mt][nt][3]);
                *(float4*)&dst[((mt * 8 + nt) * 32 + lane) * 4] = v;
            }
    }
    __syncthreads();

    if (kg == 0) {
        const float* prt = (const float*)(smem_raw + (wm * 2 + wn) * 16384);
        const int gid = lane >> 2;
        const int tg  = lane & 3;
#pragma unroll
        for (int mt = 0; mt < 4; mt++) {
#pragma unroll
            for (int nt = 0; nt < 8; nt++) {
                float4 p = *(const float4*)&prt[((mt * 8 + nt) * 32 + lane) * 4];
                int row = m0 + wm * 64 + mt * 16 + gid;
                int col = n0 + wn * 64 + nt * 8 + tg * 2;
                float2 bb = *(const float2*)&g_bias[col];
                float2 v0 = make_float2(acc[mt][nt][0] + p.x + bb.x, acc[mt][nt][1] + p.y + bb.y);
                float2 v1 = make_float2(acc[mt][nt][2] + p.z + bb.x, acc[mt][nt][3] + p.w + bb.y);
                *(float2*)&out[(size_t)row * NTOT + col]       = v0;
                *(float2*)&out[(size_t)(row + 8) * NTOT + col] = v1;
            }
        }
    }
}

// ---------------- launch ----------------
extern "C" void kernel_launch(void* const* d_in, const int* in_sizes, int n_in,
                              void* d_out, int out_size) {
    const float* xre  = (const float*)d_in[0];
    const float* xim  = (const float*)d_in[1];
    const float* rw   = (const float*)d_in[2];
    const float* cw   = (const float*)d_in[3];
    const float* swre = (const float*)d_in[4];
    const float* swim = (const float*)d_in[5];
    const float* bre  = (const float*)d_in[6];
    const float* bim  = (const float*)d_in[7];
    float* out = (float*)d_out;

    static bool attr_set = false;
    if (!attr_set) {
        cudaFuncSetAttribute(gemm_kernel, cudaFuncAttributeMaxDynamicSharedMemorySize, SMEM_BYTES);
        attr_set = true;
    }

    prep_x<<<dim3(4096, 4), 256>>>(xre, xim);
    prep_w<<<9728, 256>>>(rw, cw, swre, swim, bre, bim);
    gemm_kernel<<<dim3(NTOT / NTILE, BDIM / MTILE), 256, SMEM_BYTES>>>(out);
}